// round 14
// baseline (speedup 1.0000x reference)
#include <cuda_runtime.h>
#include <math.h>

#define TT 4096
#define DD 1024
#define NSCAN 128
#define STH 256   // scan threads: 8 warps, 1 warp per output column (8 cols/CTA)

// ---------------- scratch (device globals: no allocation allowed) ----------------
__device__ float g_Ar[TT * DD];   // xs@Wir + bir
__device__ float g_Az[TT * DD];   // xs@Wiz + biz
__device__ float g_An[TT * DD];   // xs@Win + bin
__device__ float g_ys[TT * DD];   // scan outputs
__device__ float g_lin[TT * DD];  // xs + relu(ys)@Wl + bl (pre-LN)
// tagged ping-pong hidden state: word = ((u64)step_tag << 32) | f32_bits(h)
__device__ unsigned long long g_hx[2][DD];

// ---------------- helpers ----------------
__device__ __forceinline__ unsigned long long ld_relaxed_u64(const unsigned long long* p) {
    unsigned long long v;
    asm volatile("ld.relaxed.gpu.global.u64 %0, [%1];" : "=l"(v) : "l"(p));
    return v;
}
__device__ __forceinline__ void st_release_u64(unsigned long long* p, unsigned long long v) {
    asm volatile("st.release.gpu.global.u64 [%0], %1;" :: "l"(p), "l"(v) : "memory");
}
__device__ __forceinline__ void fence_acq_rel_gpu() {
    asm volatile("fence.acq_rel.gpu;" ::: "memory");
}
__device__ __forceinline__ float fast_sigmoid(float x) {
    return 1.f / (1.f + __expf(-x));
}
__device__ __forceinline__ float fast_tanh(float x) {
    return 1.f - 2.f / (1.f + __expf(2.f * x));
}

// ---------------- per-replay init: seed h_0 with tag 0 ----------------
__global__ void hx_init_kernel(const float* __restrict__ hini) {
    const int j = blockIdx.x * 256 + threadIdx.x;
    if (j < DD) {
        g_hx[0][j] = (unsigned long long)__float_as_uint(hini[j]);  // tag 0 | h0 bits
        g_hx[1][j] = 0xFFFFFFFF00000000ull;                         // never-matching tag
    }
}

// ---------------- persistent GRU scan, dataflow-synchronized ----------------
// 128 CTAs, each owns 8 columns j = cta*8 + w (one warp per column).
// Recurrent weights register-resident (24 float4/lane). No grid barrier:
// each h element carries its step tag; consumers spin directly on the data.
// WAR safety: tag t is released AFTER the producer finished reading buffer
// (t-1)&1, so once a consumer sees all tags==t it may overwrite that buffer.
__global__ void __launch_bounds__(STH, 1) scan_kernel(
    const float* __restrict__ Whr, const float* __restrict__ Whz,
    const float* __restrict__ Whn, const float* __restrict__ bhn)
{
    __shared__ float hs[DD];

    const int tid  = threadIdx.x;
    const int cta  = blockIdx.x;
    const int w    = tid >> 5;
    const int lane = tid & 31;
    const int j    = cta * 8 + w;
    const int base = tid * 4;        // this thread's 4 h elements (32B sector)

    // one-time weight load into registers: lane covers k = 4*(lane+32*i) .. +3
    float4 wr[8], wz[8], wn[8];
    #pragma unroll
    for (int i = 0; i < 8; ++i) {
        const int k = 4 * (lane + 32 * i);
        wr[i] = make_float4(Whr[(size_t)(k + 0) * DD + j], Whr[(size_t)(k + 1) * DD + j],
                            Whr[(size_t)(k + 2) * DD + j], Whr[(size_t)(k + 3) * DD + j]);
        wz[i] = make_float4(Whz[(size_t)(k + 0) * DD + j], Whz[(size_t)(k + 1) * DD + j],
                            Whz[(size_t)(k + 2) * DD + j], Whz[(size_t)(k + 3) * DD + j]);
        wn[i] = make_float4(Whn[(size_t)(k + 0) * DD + j], Whn[(size_t)(k + 1) * DD + j],
                            Whn[(size_t)(k + 2) * DD + j], Whn[(size_t)(k + 3) * DD + j]);
    }
    const float bh = bhn[j];

    // prefetch input-projection terms for t=0 (lane 0 only)
    float ar = 0.f, az = 0.f, an = 0.f;
    if (lane == 0) { ar = g_Ar[j]; az = g_Az[j]; an = g_An[j]; }

    for (int t = 0; t < TT; ++t) {
        // ---- gather h_t: spin on tags, each thread owns 4 elements ----
        const unsigned want = (unsigned)t;
        const unsigned long long* buf = g_hx[t & 1];
        unsigned long long v0, v1, v2, v3;
        bool p0 = false, p1 = false, p2 = false, p3 = false;
        do {
            if (!p0) { v0 = ld_relaxed_u64(buf + base + 0); p0 = ((unsigned)(v0 >> 32)) == want; }
            if (!p1) { v1 = ld_relaxed_u64(buf + base + 1); p1 = ((unsigned)(v1 >> 32)) == want; }
            if (!p2) { v2 = ld_relaxed_u64(buf + base + 2); p2 = ((unsigned)(v2 >> 32)) == want; }
            if (!p3) { v3 = ld_relaxed_u64(buf + base + 3); p3 = ((unsigned)(v3 >> 32)) == want; }
        } while (!(p0 && p1 && p2 && p3));
        fence_acq_rel_gpu();             // acquire: order our later stores after these reads
        hs[base + 0] = __uint_as_float((unsigned)v0);
        hs[base + 1] = __uint_as_float((unsigned)v1);
        hs[base + 2] = __uint_as_float((unsigned)v2);
        hs[base + 3] = __uint_as_float((unsigned)v3);
        __syncthreads();

        // ---- 3 dot products of length 1024, weights in registers ----
        const float4* hs4 = (const float4*)hs;
        float accr = 0.f, accz = 0.f, accn = 0.f;
        #pragma unroll
        for (int i = 0; i < 8; ++i) {
            const float4 hv = hs4[lane + 32 * i];
            accr = fmaf(hv.x, wr[i].x, fmaf(hv.y, wr[i].y, fmaf(hv.z, wr[i].z, fmaf(hv.w, wr[i].w, accr))));
            accz = fmaf(hv.x, wz[i].x, fmaf(hv.y, wz[i].y, fmaf(hv.z, wz[i].z, fmaf(hv.w, wz[i].w, accz))));
            accn = fmaf(hv.x, wn[i].x, fmaf(hv.y, wn[i].y, fmaf(hv.z, wn[i].z, fmaf(hv.w, wn[i].w, accn))));
        }
        #pragma unroll
        for (int off = 16; off > 0; off >>= 1) {
            accr += __shfl_xor_sync(0xffffffffu, accr, off);
            accz += __shfl_xor_sync(0xffffffffu, accz, off);
            accn += __shfl_xor_sync(0xffffffffu, accn, off);
        }
        if (lane == 0) {
            const float hprev = hs[j];
            const float r  = fast_sigmoid(ar + accr);
            const float z  = fast_sigmoid(az + accz);
            const float n  = fast_tanh(an + r * (accn + bh));
            const float hn = (1.f - z) * n + z * hprev;
            // publish h_{t+1}: tag+value in one atomic 64-bit release store
            st_release_u64(&g_hx[(t + 1) & 1][j],
                           ((unsigned long long)(unsigned)(t + 1) << 32) |
                           (unsigned long long)__float_as_uint(hn));
            g_ys[(size_t)t * DD + j] = hn;
            if (t + 1 < TT) {            // prefetch next step's A terms
                const size_t o = (size_t)(t + 1) * DD + j;
                ar = g_Ar[o]; az = g_Az[o]; an = g_An[o];
            }
        }
        __syncthreads();                 // protect hs before next step's overwrite
    }
}

// ---------------- fp32 SGEMM: C[M,N] = op(A)[M,K] @ B[K,N] + bias (+ resid) ----------------
// 128x128 tile, BK=8, 256 threads, 8x8 micro-tile. op = optional relu on A.
// blockIdx.z selects among up to 3 (B, bias, C) triples (fused multi-GEMM).
template <bool RELU, bool RESID>
__global__ void __launch_bounds__(256) sgemm_kernel(
    const float* __restrict__ A,
    const float* __restrict__ B0, const float* __restrict__ B1, const float* __restrict__ B2,
    const float* __restrict__ bias0, const float* __restrict__ bias1, const float* __restrict__ bias2,
    const float* __restrict__ resid,
    float* __restrict__ C0, float* __restrict__ C1, float* __restrict__ C2,
    int M, int N, int K)
{
    const int z = blockIdx.z;
    const float* B    = (z == 0) ? B0    : (z == 1) ? B1    : B2;
    const float* bias = (z == 0) ? bias0 : (z == 1) ? bias1 : bias2;
    float*       C    = (z == 0) ? C0    : (z == 1) ? C1    : C2;

    __shared__ float As[8][128];
    __shared__ float Bs[8][128];
    const int tid = threadIdx.x;
    const int bx = blockIdx.x, by = blockIdx.y;

    const int arow = tid >> 1;         // 0..127
    const int acol = (tid & 1) << 2;   // 0 or 4
    const int brow = tid >> 5;         // 0..7
    const int bcol = (tid & 31) << 2;  // 0..124
    const int tx = tid & 15;
    const int ty = tid >> 4;

    const float* Ab = A + (size_t)by * 128 * K;
    const float* Bb = B + bx * 128;

    float acc[8][8];
    #pragma unroll
    for (int i = 0; i < 8; ++i)
        #pragma unroll
        for (int jj = 0; jj < 8; ++jj) acc[i][jj] = 0.f;

    float4 aReg = *(const float4*)(Ab + (size_t)arow * K + acol);
    float4 bReg = *(const float4*)(Bb + (size_t)brow * N + bcol);

    for (int k0 = 0; k0 < K; k0 += 8) {
        float4 av = aReg;
        if (RELU) {
            av.x = fmaxf(av.x, 0.f); av.y = fmaxf(av.y, 0.f);
            av.z = fmaxf(av.z, 0.f); av.w = fmaxf(av.w, 0.f);
        }
        As[acol + 0][arow] = av.x;
        As[acol + 1][arow] = av.y;
        As[acol + 2][arow] = av.z;
        As[acol + 3][arow] = av.w;
        *(float4*)&Bs[brow][bcol] = bReg;
        __syncthreads();
        if (k0 + 8 < K) {   // prefetch next tile during compute
            aReg = *(const float4*)(Ab + (size_t)arow * K + (k0 + 8) + acol);
            bReg = *(const float4*)(Bb + (size_t)(k0 + 8 + brow) * N + bcol);
        }
        #pragma unroll
        for (int kk = 0; kk < 8; ++kk) {
            float a[8], b[8];
            *(float4*)&a[0] = *(const float4*)&As[kk][ty * 8];
            *(float4*)&a[4] = *(const float4*)&As[kk][ty * 8 + 4];
            *(float4*)&b[0] = *(const float4*)&Bs[kk][tx * 8];
            *(float4*)&b[4] = *(const float4*)&Bs[kk][tx * 8 + 4];
            #pragma unroll
            for (int i = 0; i < 8; ++i)
                #pragma unroll
                for (int jj = 0; jj < 8; ++jj)
                    acc[i][jj] = fmaf(a[i], b[jj], acc[i][jj]);
        }
        __syncthreads();
    }

    const int nbase = bx * 128 + tx * 8;
    const float4 b0 = *(const float4*)(bias + nbase);
    const float4 b1 = *(const float4*)(bias + nbase + 4);
    #pragma unroll
    for (int i = 0; i < 8; ++i) {
        const int m = by * 128 + ty * 8 + i;
        float4 c0, c1;
        c0.x = acc[i][0] + b0.x; c0.y = acc[i][1] + b0.y;
        c0.z = acc[i][2] + b0.z; c0.w = acc[i][3] + b0.w;
        c1.x = acc[i][4] + b1.x; c1.y = acc[i][5] + b1.y;
        c1.z = acc[i][6] + b1.z; c1.w = acc[i][7] + b1.w;
        if (RESID) {
            const float4 r0 = *(const float4*)(resid + (size_t)m * N + nbase);
            const float4 r1 = *(const float4*)(resid + (size_t)m * N + nbase + 4);
            c0.x += r0.x; c0.y += r0.y; c0.z += r0.z; c0.w += r0.w;
            c1.x += r1.x; c1.y += r1.y; c1.z += r1.z; c1.w += r1.w;
        }
        *(float4*)(C + (size_t)m * N + nbase)     = c0;
        *(float4*)(C + (size_t)m * N + nbase + 4) = c1;
    }
}

// ---------------- layernorm over last dim ----------------
__global__ void __launch_bounds__(256) ln_kernel(
    const float* __restrict__ lin, const float* __restrict__ scale,
    const float* __restrict__ bias, float* __restrict__ out)
{
    const int t = blockIdx.x;
    const int tid = threadIdx.x;
    const int w = tid >> 5, lane = tid & 31;
    const float4 v = ((const float4*)(lin + (size_t)t * DD))[tid];
    float s = v.x + v.y + v.z + v.w;
    float q = v.x * v.x + v.y * v.y + v.z * v.z + v.w * v.w;
    #pragma unroll
    for (int off = 16; off > 0; off >>= 1) {
        s += __shfl_xor_sync(0xffffffffu, s, off);
        q += __shfl_xor_sync(0xffffffffu, q, off);
    }
    __shared__ float ss[8], qs[8];
    __shared__ float sMean, sInv;
    if (lane == 0) { ss[w] = s; qs[w] = q; }
    __syncthreads();
    if (tid == 0) {
        float S = 0.f, Q = 0.f;
        #pragma unroll
        for (int i = 0; i < 8; ++i) { S += ss[i]; Q += qs[i]; }
        const float mean = S * (1.0f / DD);
        const float var  = Q * (1.0f / DD) - mean * mean;
        sMean = mean;
        sInv  = rsqrtf(var + 1e-6f);
    }
    __syncthreads();
    const float mean = sMean, inv = sInv;
    const float4 sc = ((const float4*)scale)[tid];
    const float4 bi = ((const float4*)bias)[tid];
    float4 o;
    o.x = (v.x - mean) * inv * sc.x + bi.x;
    o.y = (v.y - mean) * inv * sc.y + bi.y;
    o.z = (v.z - mean) * inv * sc.z + bi.z;
    o.w = (v.w - mean) * inv * sc.w + bi.w;
    ((float4*)(out + (size_t)t * DD))[tid] = o;
}

// ---------------- launch ----------------
extern "C" void kernel_launch(void* const* d_in, const int* in_sizes, int n_in,
                              void* d_out, int out_size) {
    (void)in_sizes; (void)n_in; (void)out_size;
    const float* xs   = (const float*)d_in[0];
    const float* hini = (const float*)d_in[1];
    const float* Wir  = (const float*)d_in[2];
    const float* Wiz  = (const float*)d_in[3];
    const float* Win  = (const float*)d_in[4];
    const float* bir  = (const float*)d_in[5];
    const float* biz  = (const float*)d_in[6];
    const float* bin_ = (const float*)d_in[7];
    const float* Whr  = (const float*)d_in[8];
    const float* Whz  = (const float*)d_in[9];
    const float* Whn  = (const float*)d_in[10];
    const float* bhn  = (const float*)d_in[11];
    const float* Wl   = (const float*)d_in[12];
    const float* bl   = (const float*)d_in[13];
    const float* lns  = (const float*)d_in[14];
    const float* lnb  = (const float*)d_in[15];
    float* out = (float*)d_out;

    float *Ar, *Az, *An, *ys, *lin;
    cudaGetSymbolAddress((void**)&Ar,  g_Ar);
    cudaGetSymbolAddress((void**)&Az,  g_Az);
    cudaGetSymbolAddress((void**)&An,  g_An);
    cudaGetSymbolAddress((void**)&ys,  g_ys);
    cudaGetSymbolAddress((void**)&lin, g_lin);

    // per-replay tagged-state init (device globals persist across graph replays)
    hx_init_kernel<<<4, 256>>>(hini);

    // input projections (bias fused), all three in one launch via grid.z
    dim3 grid3(DD / 128, TT / 128, 3);
    sgemm_kernel<false, false><<<grid3, 256>>>(
        xs, Wir, Wiz, Win, bir, biz, bin_, nullptr, Ar, Az, An, TT, DD, DD);

    // persistent scan (weights register-resident; dataflow sync, no grid barrier)
    scan_kernel<<<NSCAN, STH>>>(Whr, Whz, Whn, bhn);

    // out dense: lin = xs + relu(ys)@Wl + bl, then LN
    dim3 grid1(DD / 128, TT / 128, 1);
    sgemm_kernel<true, true><<<grid1, 256>>>(
        ys, Wl, nullptr, nullptr, bl, nullptr, nullptr, xs, lin, nullptr, nullptr, TT, DD, DD);
    ln_kernel<<<TT, 256>>>(lin, lns, lnb, out);
}